// round 9
// baseline (speedup 1.0000x reference)
#include <cuda_runtime.h>

// MI loss over two 2^25 fp32 arrays — split kernels (fused was 2x-tested
// slower: per-block __threadfence = CCTL.IVALL L1D flushes mid-stream).
// joint_hist == hist_x + hist_y -> only two 30-bin histograms needed.
// hist_kernel: R5's measured-fastest loop (grid-stride, unroll 8,
// launch_bounds(256,7)), per-lane-private smem histogram (bank==lane,
// conflict-free, no atomics in hot loop), then 60 spread global
// atomicAdds per block straight into g_hist (no g_part round-trip).
// mi_kernel: one warp reads 64 ints, lane-parallel fp64 logs, writes the
// scalar, resets g_hist for graph-replay determinism.

#define BINS 30
#define NBIN_PAD 32          // 30 bins + trash slot 30 (never flushed)
#define THREADS 256
#define WARPS (THREADS / 32)
#define BPA 518              // blocks per array; 2*518 = 1036 = 7 per SM

__device__ unsigned int g_hist[2 * NBIN_PAD];  // BSS zero; mi_kernel resets

__global__ void __launch_bounds__(THREADS, 7) hist_kernel(
    const float* __restrict__ x, const float* __restrict__ y,
    int nx, int ny)
{
    // 8 warps * 32 slots * 32 lanes * 4B = 32 KB
    __shared__ unsigned int sh[WARPS * NBIN_PAD * 32];

    for (int i = threadIdx.x; i < WARPS * NBIN_PAD * 32; i += THREADS) sh[i] = 0u;
    __syncthreads();

    const int which = (blockIdx.x >= BPA) ? 1 : 0;
    const float* __restrict__ src = which ? y : x;
    const int n = which ? ny : nx;
    const int bid = which ? ((int)blockIdx.x - BPA) : (int)blockIdx.x;

    const int warp = threadIdx.x >> 5;
    const int lane = threadIdx.x & 31;
    // lane-private column: addr = warp*4096B + slot*128B + lane*4B
    // bank(addr) == lane for every slot -> conflict-free RMW.
    unsigned int* __restrict__ h = sh + warp * (NBIN_PAD * 32) + lane;

    const float4* __restrict__ v4 = (const float4*)src;
    const int n4 = n >> 2;
    const int stride = BPA * THREADS;

    // R3-exact binning (rel_err 7.28e-7): t = fma(v,3.75,15);
    // b = min(floor(t), 29); out-of-range -> trash slot 30.
#define PROC(val) {                                          \
        float t = fmaf((val), 3.75f, 15.0f);                 \
        int b = __float2int_rd(t);                           \
        b = min(b, 29);                                      \
        bool ok = (t >= 0.0f) && (t <= 30.0f);               \
        if (!ok) b = 30;                                     \
        h[b << 5] += 1u; }

    // Measured-fastest loop shape: let ptxas pipeline it.
    #pragma unroll 8
    for (int i = bid * THREADS + threadIdx.x; i < n4; i += stride) {
        float4 v = v4[i];
        PROC(v.x) PROC(v.y) PROC(v.z) PROC(v.w)
    }

    // scalar tail (empty when n % 4 == 0)
    if (bid == 0) {
        for (int j = (n4 << 2) + threadIdx.x; j < n; j += THREADS) {
            float val = src[j];
            PROC(val)
        }
    }
#undef PROC

    __syncthreads();

    // Reduce 30 bins x 32 lanes over 8 warp-copies -> 60 spread global
    // atomics per block (REDG-cheap; kernel boundary provides ordering).
    for (int p = threadIdx.x; p < BINS * 32; p += THREADS) {
        int b = p >> 5;
        int l = p & 31;
        unsigned int s = 0;
        #pragma unroll
        for (int w = 0; w < WARPS; w++)
            s += sh[w * (NBIN_PAD * 32) + (b << 5) + l];
        #pragma unroll
        for (int off = 16; off; off >>= 1)
            s += __shfl_xor_sync(0xffffffffu, s, off);
        if (l == 0 && s)
            atomicAdd(&g_hist[which * NBIN_PAD + b], s);
    }
}

__global__ void __launch_bounds__(32) mi_kernel(float* __restrict__ out) {
    const int lane = threadIdx.x;
    bool live = (lane < BINS);

    unsigned int ux = g_hist[lane];             // slots 0..31
    unsigned int uy = g_hist[NBIN_PAD + lane];  // slots 32..63
    double hx = live ? (double)ux : 0.0;
    double hy = live ? (double)uy : 0.0;

    double Sx = hx, Sy = hy;
    #pragma unroll
    for (int off = 16; off; off >>= 1) {
        Sx += __shfl_xor_sync(0xffffffffu, Sx, off);
        Sy += __shfl_xor_sync(0xffffffffu, Sy, off);
    }
    double Sj = Sx + Sy;

    double term = 0.0, lx = 0.0;
    if (live) {
        double jp = (hx + hy) / Sj;
        double py = hy / Sy;
        double px = hx / Sx;
        term = jp * (log(jp) - log(py));
        lx = log(px);
    }
    #pragma unroll
    for (int off = 16; off; off >>= 1) {
        term += __shfl_xor_sync(0xffffffffu, term, off);
        lx   += __shfl_xor_sync(0xffffffffu, lx, off);
    }
    if (lane == 0) {
        double mi = (double)BINS * term - lx;
        out[0] = (float)(-mi);
    }

    // Reset for next graph replay (same-lane program order after reads).
    g_hist[lane] = 0u;
    g_hist[NBIN_PAD + lane] = 0u;
}

extern "C" void kernel_launch(void* const* d_in, const int* in_sizes, int n_in,
                              void* d_out, int out_size) {
    const float* x = (const float*)d_in[0];
    const float* y = (const float*)d_in[1];
    int nx = in_sizes[0];
    int ny = in_sizes[1];

    hist_kernel<<<2 * BPA, THREADS>>>(x, y, nx, ny);
    mi_kernel<<<1, 32>>>((float*)d_out);
}

// round 13
// speedup vs baseline: 1.1271x; 1.1271x over previous
#include <cuda_runtime.h>

// MI loss over two 2^25 fp32 arrays — split kernels.
// joint_hist == hist_x + hist_y -> only two 30-bin histograms needed.
// hist_kernel: software-pipelined prefetch (next float4 load issued before
// processing current -> loads always in flight during the smem RMW chain;
// targets the 40% load-duty-cycle bottleneck seen in R6-R9 profiles).
// Per-lane-private smem histogram (bank==lane, conflict-free, no atomics).
// Branchless 7-inst binning: floor + unsigned clamp to trash slots.
// Flush: 60 spread global atomicAdds per block. mi_kernel: one warp,
// fp32 logs, resets g_hist for graph-replay determinism.
// (Third submission of this design: R10/R11 both hit GB300 container
// infra failures; kernel never executed.)

#define BINS 30
#define NBIN_PAD 32          // 30 bins + trash slots 30/31 (never flushed)
#define THREADS 256
#define WARPS (THREADS / 32)
#define BPA 518              // blocks per array; 2*518 = 1036 blocks

__device__ unsigned int g_hist[2 * NBIN_PAD];  // BSS zero; mi_kernel resets

__global__ void __launch_bounds__(THREADS, 6) hist_kernel(
    const float* __restrict__ x, const float* __restrict__ y,
    int nx, int ny)
{
    // 8 warps * 32 slots * 32 lanes * 4B = 32 KB
    __shared__ unsigned int sh[WARPS * NBIN_PAD * 32];

    for (int i = threadIdx.x; i < WARPS * NBIN_PAD * 32; i += THREADS) sh[i] = 0u;
    __syncthreads();

    const int which = (blockIdx.x >= BPA) ? 1 : 0;
    const float* __restrict__ src = which ? y : x;
    const int n = which ? ny : nx;
    const int bid = which ? ((int)blockIdx.x - BPA) : (int)blockIdx.x;

    const int warp = threadIdx.x >> 5;
    const int lane = threadIdx.x & 31;
    // lane-private column: addr = warp*4096B + slot*128B + lane*4B
    // bank(addr) == lane for every slot -> conflict-free RMW.
    unsigned int* __restrict__ h = sh + warp * (NBIN_PAD * 32) + lane;

    const float4* __restrict__ v4 = (const float4*)src;
    const int n4 = n >> 2;
    const int stride = BPA * THREADS;

    // Branchless binning, value-identical to the verified R3/R5 formula
    // for all inputs except exact v==+4.0 (measure-zero; <=1-count):
    //   t = fma(v,3.75,15); b = floor(t)
    //   t in [0,30) -> b in [0,29]  (valid bins, bit-identical)
    //   t < 0       -> b < 0 -> as-unsigned huge -> clamp -> 31 (trash)
    //   t >= 30     -> b >= 30 -> clamp -> 30 or 31            (trash)
    // NaN-free input by construction (random normal).
#define PROC(val) {                                          \
        float t = fmaf((val), 3.75f, 15.0f);                 \
        int b = __float2int_rd(t);                           \
        unsigned int ub = (unsigned int)b;                   \
        ub = (ub > 31u) ? 31u : ub;   /* IMNMX.U32 */        \
        h[ub << 5] += 1u; }

#define PROC4(v) { PROC((v).x) PROC((v).y) PROC((v).z) PROC((v).w) }

    // Software-pipelined: next load issues before current is processed,
    // so (with unroll 4) ~4 loads stay in flight through the RMW chains.
    int i = bid * THREADS + threadIdx.x;
    const bool valid = (i < n4);
    float4 cur;
    if (valid) cur = v4[i];
    #pragma unroll 4
    for (; i + stride < n4; i += stride) {
        float4 nxt = v4[i + stride];
        PROC4(cur)
        cur = nxt;
    }
    if (valid) PROC4(cur)

    // scalar tail (empty when n % 4 == 0)
    if (bid == 0) {
        for (int j = (n4 << 2) + threadIdx.x; j < n; j += THREADS) {
            float val = src[j];
            PROC(val)
        }
    }
#undef PROC4
#undef PROC

    __syncthreads();

    // Reduce 30 bins x 32 lanes over 8 warp-copies -> 60 spread global
    // atomics per block (kernel boundary provides ordering for mi_kernel).
    for (int p = threadIdx.x; p < BINS * 32; p += THREADS) {
        int b = p >> 5;
        int l = p & 31;
        unsigned int s = 0;
        #pragma unroll
        for (int w = 0; w < WARPS; w++)
            s += sh[w * (NBIN_PAD * 32) + (b << 5) + l];
        #pragma unroll
        for (int off = 16; off; off >>= 1)
            s += __shfl_xor_sync(0xffffffffu, s, off);
        if (l == 0 && s)
            atomicAdd(&g_hist[which * NBIN_PAD + b], s);
    }
}

__global__ void __launch_bounds__(32) mi_kernel(float* __restrict__ out) {
    const int lane = threadIdx.x;
    bool live = (lane < BINS);

    unsigned int ux = g_hist[lane];
    unsigned int uy = g_hist[NBIN_PAD + lane];
    float hx = live ? (float)ux : 0.0f;
    float hy = live ? (float)uy : 0.0f;

    float Sx = hx, Sy = hy;
    #pragma unroll
    for (int off = 16; off; off >>= 1) {
        Sx += __shfl_xor_sync(0xffffffffu, Sx, off);
        Sy += __shfl_xor_sync(0xffffffffu, Sy, off);
    }
    float Sj = Sx + Sy;

    // fp32 is ample: counts < 2^26 -> sums ~1e-7 rel; logf ~1e-7 rel;
    // tolerance is 1e-3 on an O(1..100) scalar.
    float term = 0.0f, lx = 0.0f;
    if (live) {
        float jp = (hx + hy) / Sj;
        float py = hy / Sy;
        float px = hx / Sx;
        term = jp * (logf(jp) - logf(py));
        lx = logf(px);
    }
    #pragma unroll
    for (int off = 16; off; off >>= 1) {
        term += __shfl_xor_sync(0xffffffffu, term, off);
        lx   += __shfl_xor_sync(0xffffffffu, lx, off);
    }
    if (lane == 0) {
        float mi = (float)BINS * term - lx;
        out[0] = -mi;
    }

    // Reset for next graph replay (same-lane program order after reads).
    g_hist[lane] = 0u;
    g_hist[NBIN_PAD + lane] = 0u;
}

extern "C" void kernel_launch(void* const* d_in, const int* in_sizes, int n_in,
                              void* d_out, int out_size) {
    const float* x = (const float*)d_in[0];
    const float* y = (const float*)d_in[1];
    int nx = in_sizes[0];
    int ny = in_sizes[1];

    hist_kernel<<<2 * BPA, THREADS>>>(x, y, nx, ny);
    mi_kernel<<<1, 32>>>((float*)d_out);
}

// round 15
// speedup vs baseline: 1.3120x; 1.1640x over previous
#include <cuda_runtime.h>

// MI loss over two 2^25 fp32 arrays — split kernels.
// joint_hist == hist_x + hist_y -> only two 30-bin histograms needed.
// hist_kernel: depth-2 software-pipelined prefetch (two float4 loads in
// flight per thread through the smem RMW chains), per-lane-private smem
// histogram (bank==lane, conflict-free, no atomics in hot loop),
// branchless 7-inst binning (floor + unsigned clamp to trash slots).
// Flush: 60 global atomicAdds per block, each bin in its OWN 128B line
// (R9's 2-line g_hist funneled 62k atomics into 2 LTS slices -> ~10us
// serialization tail; padding spreads them across ~60 slices).
// mi_kernel: one warp, fp32 logs, resets state for graph-replay.

#define BINS 30
#define NBIN_PAD 32          // 30 bins + trash slots 30/31 (never flushed)
#define THREADS 256
#define WARPS (THREADS / 32)
#define BPA 518              // blocks per array; 2*518 = 1036 blocks
#define LINE 32              // u32s per 128B line (bin padding stride)

// One 128B line per bin: bin r lives at g_hist[r * LINE].
__device__ unsigned int g_hist[2 * NBIN_PAD * LINE];  // BSS zero; mi resets

__global__ void __launch_bounds__(THREADS, 6) hist_kernel(
    const float* __restrict__ x, const float* __restrict__ y,
    int nx, int ny)
{
    // 8 warps * 32 slots * 32 lanes * 4B = 32 KB
    __shared__ unsigned int sh[WARPS * NBIN_PAD * 32];

    for (int i = threadIdx.x; i < WARPS * NBIN_PAD * 32; i += THREADS) sh[i] = 0u;
    __syncthreads();

    const int which = (blockIdx.x >= BPA) ? 1 : 0;
    const float* __restrict__ src = which ? y : x;
    const int n = which ? ny : nx;
    const int bid = which ? ((int)blockIdx.x - BPA) : (int)blockIdx.x;

    const int warp = threadIdx.x >> 5;
    const int lane = threadIdx.x & 31;
    // lane-private column: addr = warp*4096B + slot*128B + lane*4B
    // bank(addr) == lane for every slot -> conflict-free RMW.
    unsigned int* __restrict__ h = sh + warp * (NBIN_PAD * 32) + lane;

    const float4* __restrict__ v4 = (const float4*)src;
    const int n4 = n >> 2;
    const int stride = BPA * THREADS;

    // Branchless binning, value-identical to the verified formula for all
    // inputs except exact v==+4.0 (measure-zero; <=1-count):
    //   t = fma(v,3.75,15); b = floor(t)
    //   t in [0,30) -> b in [0,29]  (valid bins, bit-identical)
    //   t < 0       -> as-unsigned huge -> clamp -> 31 (trash)
    //   t >= 30     -> clamp -> 30 or 31               (trash)
#define PROC(val) {                                          \
        float t = fmaf((val), 3.75f, 15.0f);                 \
        int b = __float2int_rd(t);                           \
        unsigned int ub = (unsigned int)b;                   \
        ub = (ub > 31u) ? 31u : ub;   /* IMNMX.U32 */        \
        h[ub << 5] += 1u; }

#define PROC4(v) { PROC((v).x) PROC((v).y) PROC((v).z) PROC((v).w) }

    // Depth-2 software pipeline: two loads in flight while processing.
    int i = bid * THREADS + threadIdx.x;
    float4 a, b;
    if (i < n4) a = v4[i];
    if (i + stride < n4) b = v4[i + stride];
    #pragma unroll 4
    for (; i + 2 * stride < n4; i += stride) {
        float4 c = v4[i + 2 * stride];
        PROC4(a)
        a = b;
        b = c;
    }
    if (i < n4)          PROC4(a)
    if (i + stride < n4) PROC4(b)

    // scalar tail (empty when n % 4 == 0)
    if (bid == 0) {
        for (int j = (n4 << 2) + threadIdx.x; j < n; j += THREADS) {
            float val = src[j];
            PROC(val)
        }
    }
#undef PROC4
#undef PROC

    __syncthreads();

    // Reduce 30 bins x 32 lanes over 8 warp-copies -> 60 global atomics
    // per block, each to its own 128B line (spread across LTS slices).
    for (int p = threadIdx.x; p < BINS * 32; p += THREADS) {
        int bb = p >> 5;
        int l = p & 31;
        unsigned int s = 0;
        #pragma unroll
        for (int w = 0; w < WARPS; w++)
            s += sh[w * (NBIN_PAD * 32) + (bb << 5) + l];
        #pragma unroll
        for (int off = 16; off; off >>= 1)
            s += __shfl_xor_sync(0xffffffffu, s, off);
        if (l == 0 && s)
            atomicAdd(&g_hist[(which * NBIN_PAD + bb) * LINE], s);
    }
}

__global__ void __launch_bounds__(32) mi_kernel(float* __restrict__ out) {
    const int lane = threadIdx.x;
    bool live = (lane < BINS);

    unsigned int ux = g_hist[lane * LINE];
    unsigned int uy = g_hist[(NBIN_PAD + lane) * LINE];
    float hx = live ? (float)ux : 0.0f;
    float hy = live ? (float)uy : 0.0f;

    float Sx = hx, Sy = hy;
    #pragma unroll
    for (int off = 16; off; off >>= 1) {
        Sx += __shfl_xor_sync(0xffffffffu, Sx, off);
        Sy += __shfl_xor_sync(0xffffffffu, Sy, off);
    }
    float Sj = Sx + Sy;

    // fp32 is ample: counts < 2^26 -> sums ~1e-7 rel; logf ~1e-7 rel;
    // tolerance is 1e-3 on an O(1..100) scalar.
    float term = 0.0f, lx = 0.0f;
    if (live) {
        float jp = (hx + hy) / Sj;
        float py = hy / Sy;
        float px = hx / Sx;
        term = jp * (logf(jp) - logf(py));
        lx = logf(px);
    }
    #pragma unroll
    for (int off = 16; off; off >>= 1) {
        term += __shfl_xor_sync(0xffffffffu, term, off);
        lx   += __shfl_xor_sync(0xffffffffu, lx, off);
    }
    if (lane == 0) {
        float mi = (float)BINS * term - lx;
        out[0] = -mi;
    }

    // Reset for next graph replay (same-lane program order after reads).
    g_hist[lane * LINE] = 0u;
    g_hist[(NBIN_PAD + lane) * LINE] = 0u;
}

extern "C" void kernel_launch(void* const* d_in, const int* in_sizes, int n_in,
                              void* d_out, int out_size) {
    const float* x = (const float*)d_in[0];
    const float* y = (const float*)d_in[1];
    int nx = in_sizes[0];
    int ny = in_sizes[1];

    hist_kernel<<<2 * BPA, THREADS>>>(x, y, nx, ny);
    mi_kernel<<<1, 32>>>((float*)d_out);
}

// round 16
// speedup vs baseline: 1.3698x; 1.0441x over previous
#include <cuda_runtime.h>

// MI loss over two 2^25 fp32 arrays — split kernels.
// joint_hist == hist_x + hist_y -> only two 30-bin histograms needed.
// hist_kernel: depth-2 software-pipelined prefetch + per-lane-private smem
// histogram. R16 change: the smem counter update is atomicAdd (-> REDS,
// fire-and-forget) instead of LDS+IADD+STS — removes the 35-cycle
// dependent RMW chain per element that kept the kernel latency-bound.
// Lane-private layout (bank==lane) means zero contention and spread-bank
// ATOMS at LSU-floor throughput.
// Flush: 60 global atomicAdds per block, one 128B line per bin.
// mi_kernel: one warp, fp32 logs, resets state for graph-replay.

#define BINS 30
#define NBIN_PAD 32          // 30 bins + trash slots 30/31 (never flushed)
#define THREADS 256
#define WARPS (THREADS / 32)
#define BPA 518              // blocks per array; 2*518 = 1036 blocks
#define LINE 32              // u32s per 128B line (bin padding stride)

// One 128B line per bin: bin r lives at g_hist[r * LINE].
__device__ unsigned int g_hist[2 * NBIN_PAD * LINE];  // BSS zero; mi resets

__global__ void __launch_bounds__(THREADS, 6) hist_kernel(
    const float* __restrict__ x, const float* __restrict__ y,
    int nx, int ny)
{
    // 8 warps * 32 slots * 32 lanes * 4B = 32 KB
    __shared__ unsigned int sh[WARPS * NBIN_PAD * 32];

    for (int i = threadIdx.x; i < WARPS * NBIN_PAD * 32; i += THREADS) sh[i] = 0u;
    __syncthreads();

    const int which = (blockIdx.x >= BPA) ? 1 : 0;
    const float* __restrict__ src = which ? y : x;
    const int n = which ? ny : nx;
    const int bid = which ? ((int)blockIdx.x - BPA) : (int)blockIdx.x;

    const int warp = threadIdx.x >> 5;
    const int lane = threadIdx.x & 31;
    // lane-private column: addr = warp*4096B + slot*128B + lane*4B
    // bank(addr) == lane for every slot -> conflict/contention-free.
    unsigned int* __restrict__ h = sh + warp * (NBIN_PAD * 32) + lane;

    const float4* __restrict__ v4 = (const float4*)src;
    const int n4 = n >> 2;
    const int stride = BPA * THREADS;

    // Branchless binning, value-identical to the verified formula for all
    // inputs except exact v==+4.0 (measure-zero; <=1-count):
    //   t = fma(v,3.75,15); b = floor(t)
    //   t in [0,30) -> b in [0,29]  (valid bins, bit-identical)
    //   t < 0       -> as-unsigned huge -> clamp -> 31 (trash)
    //   t >= 30     -> clamp -> 30 or 31               (trash)
    // Update is a fire-and-forget shared-memory reduction (REDS): no
    // load-use latency, no RMW dependency chain.
#define PROC(val) {                                          \
        float t = fmaf((val), 3.75f, 15.0f);                 \
        int b = __float2int_rd(t);                           \
        unsigned int ub = (unsigned int)b;                   \
        ub = (ub > 31u) ? 31u : ub;   /* IMNMX.U32 */        \
        atomicAdd(h + (ub << 5), 1u); }

#define PROC4(v) { PROC((v).x) PROC((v).y) PROC((v).z) PROC((v).w) }

    // Depth-2 software pipeline: two loads in flight while processing.
    int i = bid * THREADS + threadIdx.x;
    float4 a, b;
    if (i < n4) a = v4[i];
    if (i + stride < n4) b = v4[i + stride];
    #pragma unroll 4
    for (; i + 2 * stride < n4; i += stride) {
        float4 c = v4[i + 2 * stride];
        PROC4(a)
        a = b;
        b = c;
    }
    if (i < n4)          PROC4(a)
    if (i + stride < n4) PROC4(b)

    // scalar tail (empty when n % 4 == 0)
    if (bid == 0) {
        for (int j = (n4 << 2) + threadIdx.x; j < n; j += THREADS) {
            float val = src[j];
            PROC(val)
        }
    }
#undef PROC4
#undef PROC

    __syncthreads();

    // Reduce 30 bins x 32 lanes over 8 warp-copies -> 60 global atomics
    // per block, each to its own 128B line (spread across LTS slices).
    for (int p = threadIdx.x; p < BINS * 32; p += THREADS) {
        int bb = p >> 5;
        int l = p & 31;
        unsigned int s = 0;
        #pragma unroll
        for (int w = 0; w < WARPS; w++)
            s += sh[w * (NBIN_PAD * 32) + (bb << 5) + l];
        #pragma unroll
        for (int off = 16; off; off >>= 1)
            s += __shfl_xor_sync(0xffffffffu, s, off);
        if (l == 0 && s)
            atomicAdd(&g_hist[(which * NBIN_PAD + bb) * LINE], s);
    }
}

__global__ void __launch_bounds__(32) mi_kernel(float* __restrict__ out) {
    const int lane = threadIdx.x;
    bool live = (lane < BINS);

    unsigned int ux = g_hist[lane * LINE];
    unsigned int uy = g_hist[(NBIN_PAD + lane) * LINE];
    float hx = live ? (float)ux : 0.0f;
    float hy = live ? (float)uy : 0.0f;

    float Sx = hx, Sy = hy;
    #pragma unroll
    for (int off = 16; off; off >>= 1) {
        Sx += __shfl_xor_sync(0xffffffffu, Sx, off);
        Sy += __shfl_xor_sync(0xffffffffu, Sy, off);
    }
    float Sj = Sx + Sy;

    // fp32 is ample: counts < 2^26 -> sums ~1e-7 rel; logf ~1e-7 rel;
    // tolerance is 1e-3 on an O(1..100) scalar.
    float term = 0.0f, lx = 0.0f;
    if (live) {
        float jp = (hx + hy) / Sj;
        float py = hy / Sy;
        float px = hx / Sx;
        term = jp * (logf(jp) - logf(py));
        lx = logf(px);
    }
    #pragma unroll
    for (int off = 16; off; off >>= 1) {
        term += __shfl_xor_sync(0xffffffffu, term, off);
        lx   += __shfl_xor_sync(0xffffffffu, lx, off);
    }
    if (lane == 0) {
        float mi = (float)BINS * term - lx;
        out[0] = -mi;
    }

    // Reset for next graph replay (same-lane program order after reads).
    g_hist[lane * LINE] = 0u;
    g_hist[(NBIN_PAD + lane) * LINE] = 0u;
}

extern "C" void kernel_launch(void* const* d_in, const int* in_sizes, int n_in,
                              void* d_out, int out_size) {
    const float* x = (const float*)d_in[0];
    const float* y = (const float*)d_in[1];
    int nx = in_sizes[0];
    int ny = in_sizes[1];

    hist_kernel<<<2 * BPA, THREADS>>>(x, y, nx, ny);
    mi_kernel<<<1, 32>>>((float*)d_out);
}

// round 17
// speedup vs baseline: 1.6417x; 1.1985x over previous
#include <cuda_runtime.h>

// MI loss over two 2^25 fp32 arrays — split kernels.
// joint_hist == hist_x + hist_y -> only two 30-bin histograms needed.
// hist_kernel: depth-2 software-pipelined prefetch; smem histogram updated
// with fire-and-forget shared-memory atomicAdd (REDS). R17 change: warp
// PAIRS share a histogram copy (REDS makes races safe) -> 16 KB smem/block
// -> 8 blocks/SM, 64 warps/SM (was 32 KB / 7 blocks / occ 65%). Attacks
// the one depressed profile metric: achieved occupancy.
// Lane-private columns (bank==lane) keep accesses conflict-free.
// Flush: 60 global atomicAdds per block, one 128B line per bin.
// mi_kernel: one warp, fp32 logs, resets state for graph-replay.

#define BINS 30
#define NBIN_PAD 32          // 30 bins + trash slots 30/31 (never flushed)
#define THREADS 256
#define NCOPY 4              // histogram copies; warps w and w+4 share
#define BPA 592              // blocks per array; 2*592 = 1184 = 8 per SM
#define LINE 32              // u32s per 128B line (bin padding stride)

// One 128B line per bin: bin r lives at g_hist[r * LINE].
__device__ unsigned int g_hist[2 * NBIN_PAD * LINE];  // BSS zero; mi resets

__global__ void __launch_bounds__(THREADS, 8) hist_kernel(
    const float* __restrict__ x, const float* __restrict__ y,
    int nx, int ny)
{
    // 4 copies * 32 slots * 32 lanes * 4B = 16 KB
    __shared__ unsigned int sh[NCOPY * NBIN_PAD * 32];

    for (int i = threadIdx.x; i < NCOPY * NBIN_PAD * 32; i += THREADS) sh[i] = 0u;
    __syncthreads();

    const int which = (blockIdx.x >= BPA) ? 1 : 0;
    const float* __restrict__ src = which ? y : x;
    const int n = which ? ny : nx;
    const int bid = which ? ((int)blockIdx.x - BPA) : (int)blockIdx.x;

    const int warp = threadIdx.x >> 5;
    const int lane = threadIdx.x & 31;
    // copy shared by warp pair; lane-private column within the copy:
    // addr = (warp&3)*4096B + slot*128B + lane*4B -> bank(addr) == lane.
    // REDS atomics make the warp-pair sharing race-safe.
    unsigned int* __restrict__ h = sh + (warp & (NCOPY - 1)) * (NBIN_PAD * 32) + lane;

    const float4* __restrict__ v4 = (const float4*)src;
    const int n4 = n >> 2;
    const int stride = BPA * THREADS;

    // Branchless binning, value-identical to the verified formula for all
    // inputs except exact v==+4.0 (measure-zero; <=1-count):
    //   t = fma(v,3.75,15); b = floor(t)
    //   t in [0,30) -> b in [0,29]  (valid bins, bit-identical)
    //   t < 0       -> as-unsigned huge -> clamp -> 31 (trash)
    //   t >= 30     -> clamp -> 30 or 31               (trash)
#define PROC(val) {                                          \
        float t = fmaf((val), 3.75f, 15.0f);                 \
        int b = __float2int_rd(t);                           \
        unsigned int ub = (unsigned int)b;                   \
        ub = (ub > 31u) ? 31u : ub;   /* IMNMX.U32 */        \
        atomicAdd(h + (ub << 5), 1u); }

#define PROC4(v) { PROC((v).x) PROC((v).y) PROC((v).z) PROC((v).w) }

    // Depth-2 software pipeline: two loads in flight while processing.
    int i = bid * THREADS + threadIdx.x;
    float4 a, b;
    if (i < n4) a = v4[i];
    if (i + stride < n4) b = v4[i + stride];
    #pragma unroll 4
    for (; i + 2 * stride < n4; i += stride) {
        float4 c = v4[i + 2 * stride];
        PROC4(a)
        a = b;
        b = c;
    }
    if (i < n4)          PROC4(a)
    if (i + stride < n4) PROC4(b)

    // scalar tail (empty when n % 4 == 0)
    if (bid == 0) {
        for (int j = (n4 << 2) + threadIdx.x; j < n; j += THREADS) {
            float val = src[j];
            PROC(val)
        }
    }
#undef PROC4
#undef PROC

    __syncthreads();

    // Reduce 30 bins x 32 lanes over 4 copies -> 60 global atomics per
    // block, each to its own 128B line (spread across LTS slices).
    for (int p = threadIdx.x; p < BINS * 32; p += THREADS) {
        int bb = p >> 5;
        int l = p & 31;
        unsigned int s = 0;
        #pragma unroll
        for (int w = 0; w < NCOPY; w++)
            s += sh[w * (NBIN_PAD * 32) + (bb << 5) + l];
        #pragma unroll
        for (int off = 16; off; off >>= 1)
            s += __shfl_xor_sync(0xffffffffu, s, off);
        if (l == 0 && s)
            atomicAdd(&g_hist[(which * NBIN_PAD + bb) * LINE], s);
    }
}

__global__ void __launch_bounds__(32) mi_kernel(float* __restrict__ out) {
    const int lane = threadIdx.x;
    bool live = (lane < BINS);

    unsigned int ux = g_hist[lane * LINE];
    unsigned int uy = g_hist[(NBIN_PAD + lane) * LINE];
    float hx = live ? (float)ux : 0.0f;
    float hy = live ? (float)uy : 0.0f;

    float Sx = hx, Sy = hy;
    #pragma unroll
    for (int off = 16; off; off >>= 1) {
        Sx += __shfl_xor_sync(0xffffffffu, Sx, off);
        Sy += __shfl_xor_sync(0xffffffffu, Sy, off);
    }
    float Sj = Sx + Sy;

    // fp32 is ample: counts < 2^26 -> sums ~1e-7 rel; logf ~1e-7 rel;
    // tolerance is 1e-3 on an O(1..100) scalar.
    float term = 0.0f, lx = 0.0f;
    if (live) {
        float jp = (hx + hy) / Sj;
        float py = hy / Sy;
        float px = hx / Sx;
        term = jp * (logf(jp) - logf(py));
        lx = logf(px);
    }
    #pragma unroll
    for (int off = 16; off; off >>= 1) {
        term += __shfl_xor_sync(0xffffffffu, term, off);
        lx   += __shfl_xor_sync(0xffffffffu, lx, off);
    }
    if (lane == 0) {
        float mi = (float)BINS * term - lx;
        out[0] = -mi;
    }

    // Reset for next graph replay (same-lane program order after reads).
    g_hist[lane * LINE] = 0u;
    g_hist[(NBIN_PAD + lane) * LINE] = 0u;
}

extern "C" void kernel_launch(void* const* d_in, const int* in_sizes, int n_in,
                              void* d_out, int out_size) {
    const float* x = (const float*)d_in[0];
    const float* y = (const float*)d_in[1];
    int nx = in_sizes[0];
    int ny = in_sizes[1];

    hist_kernel<<<2 * BPA, THREADS>>>(x, y, nx, ny);
    mi_kernel<<<1, 32>>>((float*)d_out);
}